// round 1
// baseline (speedup 1.0000x reference)
#include <cuda_runtime.h>
#include <math.h>

// Problem constants
#define BB   2
#define TT   4096
#define CC   768
#define HH   12
#define HD   64
#define MM   (BB*TT)        // 8192 rows
#define NQKV (3*CC)         // 2304

// Scratch (no cudaMalloc allowed): qkv = 75.5 MB, y = 25 MB
__device__ float g_qkv[(size_t)MM * NQKV];
__device__ float g_y[(size_t)MM * CC];

// ----------------------------------------------------------------------------
// SGEMM: C[M,N] = A[M,K] @ B[K,N] + bias[N]
// BM=BN=128, BK=8, TM=TN=8, 256 threads
// ----------------------------------------------------------------------------
__global__ __launch_bounds__(256)
void sgemm_bias_kernel(const float* __restrict__ A, const float* __restrict__ Bm,
                       const float* __restrict__ bias, float* __restrict__ Cm,
                       int M, int N, int K)
{
    constexpr int BM = 128, BN = 128, BK = 8, TM = 8, TN = 8;
    __shared__ float As[BK][BM];   // A stored transposed
    __shared__ float Bs[BK][BN];

    const int tid  = threadIdx.x;
    const int cRow = blockIdx.y;
    const int cCol = blockIdx.x;

    const int threadRow = tid / (BN / TN);   // 0..15
    const int threadCol = tid % (BN / TN);   // 0..15

    // A tile load: 128x8 = 1024 floats -> 1 float4 per thread
    const int aRow = tid / (BK / 4);         // 0..127
    const int aCol = (tid % (BK / 4)) * 4;   // 0 or 4
    // B tile load: 8x128 = 1024 floats -> 1 float4 per thread
    const int bRow = tid / (BN / 4);         // 0..7
    const int bCol = (tid % (BN / 4)) * 4;   // 0..124

    const float* Ab = A + (size_t)cRow * BM * K;
    const float* Bb = Bm + (size_t)cCol * BN;

    float acc[TM][TN];
#pragma unroll
    for (int i = 0; i < TM; ++i)
#pragma unroll
        for (int j = 0; j < TN; ++j) acc[i][j] = 0.f;

    for (int k0 = 0; k0 < K; k0 += BK) {
        float4 av = *(const float4*)(Ab + (size_t)aRow * K + k0 + aCol);
        As[aCol + 0][aRow] = av.x;
        As[aCol + 1][aRow] = av.y;
        As[aCol + 2][aRow] = av.z;
        As[aCol + 3][aRow] = av.w;
        float4 bv = *(const float4*)(Bb + (size_t)(k0 + bRow) * N + bCol);
        *(float4*)&Bs[bRow][bCol] = bv;
        __syncthreads();

#pragma unroll
        for (int k = 0; k < BK; ++k) {
            float regM[TM], regN[TN];
            *(float4*)&regM[0] = *(const float4*)&As[k][threadRow * TM];
            *(float4*)&regM[4] = *(const float4*)&As[k][threadRow * TM + 4];
            *(float4*)&regN[0] = *(const float4*)&Bs[k][threadCol * TN];
            *(float4*)&regN[4] = *(const float4*)&Bs[k][threadCol * TN + 4];
#pragma unroll
            for (int i = 0; i < TM; ++i)
#pragma unroll
                for (int j = 0; j < TN; ++j)
                    acc[i][j] += regM[i] * regN[j];
        }
        __syncthreads();
    }

#pragma unroll
    for (int i = 0; i < TM; ++i) {
        const int row = cRow * BM + threadRow * TM + i;
#pragma unroll
        for (int j = 0; j < TN; j += 4) {
            const int col = cCol * BN + threadCol * TN + j;
            float4 r;
            r.x = acc[i][j + 0] + bias[col + 0];
            r.y = acc[i][j + 1] + bias[col + 1];
            r.z = acc[i][j + 2] + bias[col + 2];
            r.w = acc[i][j + 3] + bias[col + 3];
            *(float4*)(Cm + (size_t)row * N + col) = r;
        }
    }
}

// ----------------------------------------------------------------------------
// Flash attention (fp32). One block per (q-tile 64, head, batch).
// 256 threads, 4x4 micro-tile over the 64x64 score tile.
// smem: Qs,Ks,Vs,Ps each [64][65] floats -> 66560 B dynamic.
// ----------------------------------------------------------------------------
#define FSTRIDE 65
#define FLASH_SMEM_BYTES (4 * 64 * FSTRIDE * sizeof(float))

__device__ __forceinline__ float warp16_max(float v) {
#pragma unroll
    for (int off = 1; off < 16; off <<= 1)
        v = fmaxf(v, __shfl_xor_sync(0xffffffffu, v, off));
    return v;
}
__device__ __forceinline__ float warp16_sum(float v) {
#pragma unroll
    for (int off = 1; off < 16; off <<= 1)
        v += __shfl_xor_sync(0xffffffffu, v, off);
    return v;
}

__global__ __launch_bounds__(256)
void flash_attn_kernel(const float* __restrict__ qkv, float* __restrict__ y)
{
    extern __shared__ float sm[];
    float* Qs = sm;                       // [64][65]
    float* Ks = Qs + 64 * FSTRIDE;        // [64][65]
    float* Vs = Ks + 64 * FSTRIDE;        // [64][65]
    float* Ps = Vs + 64 * FSTRIDE;        // [64][65]

    const int qt  = blockIdx.x;           // 0..63
    const int h   = blockIdx.y;           // 0..11
    const int b   = blockIdx.z;           // 0..1
    const int tid = threadIdx.x;
    const int ty  = tid >> 4;             // 0..15 (4 rows each)
    const int tx  = tid & 15;             // 0..15 (4 cols each)
    const int ty4 = ty * 4, tx4 = tx * 4;
    const int q0  = qt * 64;

    const size_t rowBase = (size_t)b * TT;      // token-row offset
    const size_t qOff = h * HD;                 // within 2304-wide row
    const size_t kOff = CC + h * HD;
    const size_t vOff = 2 * CC + h * HD;

    // ---- load Q tile (64 x 64) ----
#pragma unroll
    for (int p = 0; p < 4; ++p) {
        const int idx = tid + 256 * p;
        const int r = idx >> 4, c = (idx & 15) * 4;
        float4 v = *(const float4*)(qkv + (rowBase + q0 + r) * NQKV + qOff + c);
        Qs[r * FSTRIDE + c + 0] = v.x;
        Qs[r * FSTRIDE + c + 1] = v.y;
        Qs[r * FSTRIDE + c + 2] = v.z;
        Qs[r * FSTRIDE + c + 3] = v.w;
    }

    float m[4], l[4], o[4][4];
#pragma unroll
    for (int i = 0; i < 4; ++i) {
        m[i] = -INFINITY; l[i] = 0.f;
#pragma unroll
        for (int j = 0; j < 4; ++j) o[i][j] = 0.f;
    }

    const float SCALE = 0.125f;   // 1/sqrt(64)

    for (int kt = 0; kt <= qt; ++kt) {
        const int k0 = kt * 64;
        __syncthreads();   // Q visible (first iter) / previous PV done
        // ---- load K,V tiles ----
#pragma unroll
        for (int p = 0; p < 4; ++p) {
            const int idx = tid + 256 * p;
            const int r = idx >> 4, c = (idx & 15) * 4;
            const size_t grow = (rowBase + k0 + r) * NQKV;
            float4 kv = *(const float4*)(qkv + grow + kOff + c);
            Ks[r * FSTRIDE + c + 0] = kv.x;
            Ks[r * FSTRIDE + c + 1] = kv.y;
            Ks[r * FSTRIDE + c + 2] = kv.z;
            Ks[r * FSTRIDE + c + 3] = kv.w;
            float4 vv = *(const float4*)(qkv + grow + vOff + c);
            Vs[r * FSTRIDE + c + 0] = vv.x;
            Vs[r * FSTRIDE + c + 1] = vv.y;
            Vs[r * FSTRIDE + c + 2] = vv.z;
            Vs[r * FSTRIDE + c + 3] = vv.w;
        }
        __syncthreads();

        // ---- S = Q K^T (4x4 per thread) ----
        float s[4][4];
#pragma unroll
        for (int i = 0; i < 4; ++i)
#pragma unroll
            for (int j = 0; j < 4; ++j) s[i][j] = 0.f;

#pragma unroll 8
        for (int d = 0; d < HD; ++d) {
            float qv[4], kv[4];
#pragma unroll
            for (int i = 0; i < 4; ++i) qv[i] = Qs[(ty4 + i) * FSTRIDE + d];
#pragma unroll
            for (int j = 0; j < 4; ++j) kv[j] = Ks[(tx4 + j) * FSTRIDE + d];
#pragma unroll
            for (int i = 0; i < 4; ++i)
#pragma unroll
                for (int j = 0; j < 4; ++j)
                    s[i][j] += qv[i] * kv[j];
        }

        // ---- scale + causal mask ----
        const bool diag = (kt == qt);
#pragma unroll
        for (int i = 0; i < 4; ++i)
#pragma unroll
            for (int j = 0; j < 4; ++j) {
                float sv = s[i][j] * SCALE;
                if (diag && (k0 + tx4 + j) > (q0 + ty4 + i)) sv = -INFINITY;
                s[i][j] = sv;
            }

        // ---- online softmax ----
#pragma unroll
        for (int i = 0; i < 4; ++i) {
            float mx = fmaxf(fmaxf(s[i][0], s[i][1]), fmaxf(s[i][2], s[i][3]));
            mx = warp16_max(mx);
            const float mnew  = fmaxf(m[i], mx);
            const float alpha = __expf(m[i] - mnew);
            float ssum = 0.f;
#pragma unroll
            for (int j = 0; j < 4; ++j) {
                const float e = __expf(s[i][j] - mnew);
                s[i][j] = e;
                ssum += e;
            }
            ssum = warp16_sum(ssum);
            l[i] = l[i] * alpha + ssum;
            m[i] = mnew;
#pragma unroll
            for (int j = 0; j < 4; ++j) o[i][j] *= alpha;
        }

        // ---- write P ----
#pragma unroll
        for (int i = 0; i < 4; ++i)
#pragma unroll
            for (int j = 0; j < 4; ++j)
                Ps[(ty4 + i) * FSTRIDE + tx4 + j] = s[i][j];
        __syncthreads();

        // ---- O += P V ----
#pragma unroll 8
        for (int kp = 0; kp < 64; ++kp) {
            float pv[4], vv[4];
#pragma unroll
            for (int i = 0; i < 4; ++i) pv[i] = Ps[(ty4 + i) * FSTRIDE + kp];
#pragma unroll
            for (int j = 0; j < 4; ++j) vv[j] = Vs[kp * FSTRIDE + tx4 + j];
#pragma unroll
            for (int i = 0; i < 4; ++i)
#pragma unroll
                for (int j = 0; j < 4; ++j)
                    o[i][j] += pv[i] * vv[j];
        }
    }

    // ---- epilogue: O / l -> y[(b,t),(h*64+d)] ----
#pragma unroll
    for (int i = 0; i < 4; ++i) {
        const float inv = 1.f / l[i];
        const int r = q0 + ty4 + i;
        float4 w;
        w.x = o[i][0] * inv;
        w.y = o[i][1] * inv;
        w.z = o[i][2] * inv;
        w.w = o[i][3] * inv;
        *(float4*)(y + (rowBase + r) * CC + h * HD + tx4) = w;
    }
}

// ----------------------------------------------------------------------------
extern "C" void kernel_launch(void* const* d_in, const int* in_sizes, int n_in,
                              void* d_out, int out_size)
{
    // Map inputs by element count (robust to ordering)
    const float *x = nullptr, *w_attn = nullptr, *b_attn = nullptr,
                *w_proj = nullptr, *b_proj = nullptr;
    for (int i = 0; i < n_in; ++i) {
        const int s = in_sizes[i];
        const float* p = (const float*)d_in[i];
        if      (s == MM * CC)   x      = p;   // 6291456
        else if (s == CC * NQKV) w_attn = p;   // 1769472
        else if (s == NQKV)      b_attn = p;   // 2304
        else if (s == CC * CC)   w_proj = p;   // 589824
        else if (s == CC)        b_proj = p;   // 768
    }
    float* out = (float*)d_out;

    float *qkv = nullptr, *y = nullptr;
    cudaGetSymbolAddress((void**)&qkv, g_qkv);
    cudaGetSymbolAddress((void**)&y, g_y);

    cudaFuncSetAttribute(flash_attn_kernel,
                         cudaFuncAttributeMaxDynamicSharedMemorySize,
                         (int)FLASH_SMEM_BYTES);

    dim3 blk(256);
    // 1) QKV projection
    sgemm_bias_kernel<<<dim3(NQKV / 128, MM / 128), blk>>>(
        x, w_attn, b_attn, qkv, MM, NQKV, CC);
    // 2) causal flash attention
    flash_attn_kernel<<<dim3(TT / 64, HH, BB), blk, FLASH_SMEM_BYTES>>>(qkv, y);
    // 3) output projection
    sgemm_bias_kernel<<<dim3(CC / 128, MM / 128), blk>>>(
        y, w_proj, b_proj, out, MM, CC, CC);
}

// round 3
// speedup vs baseline: 1.8893x; 1.8893x over previous
#include <cuda_runtime.h>
#include <math.h>
#include <stdint.h>

// Problem constants
#define BB   2
#define TT   4096
#define CC   768
#define HH   12
#define HD   64
#define MM   (BB*TT)        // 8192 rows
#define NQKV (3*CC)         // 2304

// Scratch (no cudaMalloc allowed): qkv = 75.5 MB, y = 25 MB
__device__ float g_qkv[(size_t)MM * NQKV];
__device__ float g_y[(size_t)MM * CC];

// ----------------------------------------------------------------------------
// SGEMM: C[M,N] = A[M,K] @ B[K,N] + bias[N]  (unchanged from R0 baseline)
// ----------------------------------------------------------------------------
__global__ __launch_bounds__(256)
void sgemm_bias_kernel(const float* __restrict__ A, const float* __restrict__ Bm,
                       const float* __restrict__ bias, float* __restrict__ Cm,
                       int M, int N, int K)
{
    constexpr int BM = 128, BN = 128, BK = 8, TM = 8, TN = 8;
    __shared__ float As[BK][BM];
    __shared__ float Bs[BK][BN];

    const int tid  = threadIdx.x;
    const int cRow = blockIdx.y;
    const int cCol = blockIdx.x;

    const int threadRow = tid / (BN / TN);
    const int threadCol = tid % (BN / TN);

    const int aRow = tid / (BK / 4);
    const int aCol = (tid % (BK / 4)) * 4;
    const int bRow = tid / (BN / 4);
    const int bCol = (tid % (BN / 4)) * 4;

    const float* Ab = A + (size_t)cRow * BM * K;
    const float* Bb = Bm + (size_t)cCol * BN;

    float acc[TM][TN];
#pragma unroll
    for (int i = 0; i < TM; ++i)
#pragma unroll
        for (int j = 0; j < TN; ++j) acc[i][j] = 0.f;

    for (int k0 = 0; k0 < K; k0 += BK) {
        float4 av = *(const float4*)(Ab + (size_t)aRow * K + k0 + aCol);
        As[aCol + 0][aRow] = av.x;
        As[aCol + 1][aRow] = av.y;
        As[aCol + 2][aRow] = av.z;
        As[aCol + 3][aRow] = av.w;
        float4 bv = *(const float4*)(Bb + (size_t)(k0 + bRow) * N + bCol);
        *(float4*)&Bs[bRow][bCol] = bv;
        __syncthreads();

#pragma unroll
        for (int k = 0; k < BK; ++k) {
            float regM[TM], regN[TN];
            *(float4*)&regM[0] = *(const float4*)&As[k][threadRow * TM];
            *(float4*)&regM[4] = *(const float4*)&As[k][threadRow * TM + 4];
            *(float4*)&regN[0] = *(const float4*)&Bs[k][threadCol * TN];
            *(float4*)&regN[4] = *(const float4*)&Bs[k][threadCol * TN + 4];
#pragma unroll
            for (int i = 0; i < TM; ++i)
#pragma unroll
                for (int j = 0; j < TN; ++j)
                    acc[i][j] += regM[i] * regN[j];
        }
        __syncthreads();
    }

#pragma unroll
    for (int i = 0; i < TM; ++i) {
        const int row = cRow * BM + threadRow * TM + i;
#pragma unroll
        for (int j = 0; j < TN; j += 4) {
            const int col = cCol * BN + threadCol * TN + j;
            float4 r;
            r.x = acc[i][j + 0] + bias[col + 0];
            r.y = acc[i][j + 1] + bias[col + 1];
            r.z = acc[i][j + 2] + bias[col + 2];
            r.w = acc[i][j + 3] + bias[col + 3];
            *(float4*)(Cm + (size_t)row * N + col) = r;
        }
    }
}

// ----------------------------------------------------------------------------
// TF32 helpers
// ----------------------------------------------------------------------------
__device__ __forceinline__ float tf32r(float x) {
    uint32_t r;
    asm("cvt.rna.tf32.f32 %0, %1;" : "=r"(r) : "f"(x));
    return __uint_as_float(r);
}

__device__ __forceinline__ void mma_tf32(float* d, const uint32_t* a,
                                         uint32_t b0, uint32_t b1) {
    asm volatile(
        "mma.sync.aligned.m16n8k8.row.col.f32.tf32.tf32.f32 "
        "{%0,%1,%2,%3}, {%4,%5,%6,%7}, {%8,%9}, {%0,%1,%2,%3};\n"
        : "+f"(d[0]), "+f"(d[1]), "+f"(d[2]), "+f"(d[3])
        : "r"(a[0]), "r"(a[1]), "r"(a[2]), "r"(a[3]), "r"(b0), "r"(b1));
}

// ----------------------------------------------------------------------------
// Flash attention, tf32 tensor-core version.
// Block = 128 q-rows x (loop of) 64 kv-cols per (head, batch). 256 threads.
// Warp w owns q-rows [w*16, w*16+16). Q fragments live in registers.
// smem: Qs/Ps [128][68] (shared buffer), Ks [64][68], Vs [64][68] -> 69632 B.
// ----------------------------------------------------------------------------
#define FA_SMEM_BYTES ((128 + 64 + 64) * 68 * sizeof(float))

__global__ __launch_bounds__(256)
void flash_attn_tf32_kernel(const float* __restrict__ qkv, float* __restrict__ y)
{
    extern __shared__ float sm[];
    float* Qs = sm;                    // [128][68], reused as Ps after Q->regs
    float* Ks = sm + 128 * 68;         // [64][68]
    float* Vs = Ks + 64 * 68;          // [64][68]

    const int tid  = threadIdx.x;
    const int warp = tid >> 5;
    const int lane = tid & 31;
    const int quad = lane >> 2;        // groupID 0..7
    const int ql   = lane & 3;         // thread-in-group 0..3
    const int qb = blockIdx.x;         // 0..31
    const int h  = blockIdx.y;
    const int b  = blockIdx.z;
    const int q0 = qb * 128;
    const size_t rowBase = (size_t)b * TT;
    const int qOff = h * HD, kOff = CC + h * HD, vOff = 2 * CC + h * HD;

    // ---- load Q tile (128 x 64) into smem as tf32, coalesced ----
#pragma unroll
    for (int p = 0; p < 8; ++p) {
        const int f4 = tid + 256 * p;               // 0..2047 float4s
        const int r = f4 >> 4, c = (f4 & 15) << 2;
        const float4 v = *(const float4*)(qkv + (rowBase + q0 + r) * NQKV + qOff + c);
        Qs[r * 68 + c + 0] = tf32r(v.x);
        Qs[r * 68 + c + 1] = tf32r(v.y);
        Qs[r * 68 + c + 2] = tf32r(v.z);
        Qs[r * 68 + c + 3] = tf32r(v.w);
    }
    __syncthreads();

    // ---- Q fragments -> registers (m16n8k8 A-layout) ----
    const int rloc = warp * 16 + quad;
    uint32_t qa[8][4];
#pragma unroll
    for (int ks = 0; ks < 8; ++ks) {
        const int c = ks * 8 + ql;
        qa[ks][0] = __float_as_uint(Qs[rloc * 68 + c]);
        qa[ks][1] = __float_as_uint(Qs[(rloc + 8) * 68 + c]);
        qa[ks][2] = __float_as_uint(Qs[rloc * 68 + c + 4]);
        qa[ks][3] = __float_as_uint(Qs[(rloc + 8) * 68 + c + 4]);
    }

    float m0 = -INFINITY, m1 = -INFINITY, l0 = 0.f, l1 = 0.f;
    float o[8][4];
#pragma unroll
    for (int t = 0; t < 8; ++t) { o[t][0] = o[t][1] = o[t][2] = o[t][3] = 0.f; }

    const int qrow0 = q0 + warp * 16 + quad;
    const int qrow1 = qrow0 + 8;
    const float C2 = 0.18033688011112042f;   // log2(e) / sqrt(64)

    const int nkt = (q0 >> 6) + 2;           // kv tiles to process (causal)
    for (int kt = 0; kt < nkt; ++kt) {
        const int k0 = kt << 6;
        __syncthreads();   // prior iter's Ks/Vs reads done
        // ---- load K,V tiles (64 x 64 each) as tf32 ----
#pragma unroll
        for (int p = 0; p < 4; ++p) {
            const int f4 = tid + 256 * p;           // 0..1023
            const int r = f4 >> 4, c = (f4 & 15) << 2;
            const size_t g = (rowBase + k0 + r) * NQKV;
            const float4 kv = *(const float4*)(qkv + g + kOff + c);
            Ks[r * 68 + c + 0] = tf32r(kv.x);
            Ks[r * 68 + c + 1] = tf32r(kv.y);
            Ks[r * 68 + c + 2] = tf32r(kv.z);
            Ks[r * 68 + c + 3] = tf32r(kv.w);
            const float4 vv = *(const float4*)(qkv + g + vOff + c);
            Vs[r * 68 + c + 0] = tf32r(vv.x);
            Vs[r * 68 + c + 1] = tf32r(vv.y);
            Vs[r * 68 + c + 2] = tf32r(vv.z);
            Vs[r * 68 + c + 3] = tf32r(vv.w);
        }
        __syncthreads();

        // ---- S = Q K^T : 8 n-tiles x 8 k-steps of m16n8k8 ----
        float sacc[8][4];
#pragma unroll
        for (int t = 0; t < 8; ++t) { sacc[t][0] = sacc[t][1] = sacc[t][2] = sacc[t][3] = 0.f; }
#pragma unroll
        for (int ks = 0; ks < 8; ++ks) {
#pragma unroll
            for (int t = 0; t < 8; ++t) {
                const uint32_t b0 = __float_as_uint(Ks[(t * 8 + quad) * 68 + ks * 8 + ql]);
                const uint32_t b1 = __float_as_uint(Ks[(t * 8 + quad) * 68 + ks * 8 + ql + 4]);
                mma_tf32(sacc[t], qa[ks], b0, b1);
            }
        }

        // ---- scale (base-2 domain) + causal mask + row max ----
        float rm0 = -INFINITY, rm1 = -INFINITY;
#pragma unroll
        for (int t = 0; t < 8; ++t) {
            const int gc = k0 + t * 8 + ql * 2;
            float v0 = sacc[t][0] * C2; if (gc     > qrow0) v0 = -INFINITY;
            float v1 = sacc[t][1] * C2; if (gc + 1 > qrow0) v1 = -INFINITY;
            float v2 = sacc[t][2] * C2; if (gc     > qrow1) v2 = -INFINITY;
            float v3 = sacc[t][3] * C2; if (gc + 1 > qrow1) v3 = -INFINITY;
            sacc[t][0] = v0; sacc[t][1] = v1; sacc[t][2] = v2; sacc[t][3] = v3;
            rm0 = fmaxf(rm0, fmaxf(v0, v1));
            rm1 = fmaxf(rm1, fmaxf(v2, v3));
        }
        rm0 = fmaxf(rm0, __shfl_xor_sync(0xffffffffu, rm0, 1));
        rm0 = fmaxf(rm0, __shfl_xor_sync(0xffffffffu, rm0, 2));
        rm1 = fmaxf(rm1, __shfl_xor_sync(0xffffffffu, rm1, 1));
        rm1 = fmaxf(rm1, __shfl_xor_sync(0xffffffffu, rm1, 2));
        const float mn0 = fmaxf(m0, rm0);
        const float mn1 = fmaxf(m1, rm1);
        const float al0 = exp2f(m0 - mn0);
        const float al1 = exp2f(m1 - mn1);

        // ---- exp, P write (to Qs buffer), O rescale ----
        float* Ps = Qs;
        float sum0 = 0.f, sum1 = 0.f;
#pragma unroll
        for (int t = 0; t < 8; ++t) {
            const float p0 = exp2f(sacc[t][0] - mn0);
            const float p1 = exp2f(sacc[t][1] - mn0);
            const float p2 = exp2f(sacc[t][2] - mn1);
            const float p3 = exp2f(sacc[t][3] - mn1);
            sum0 += p0 + p1; sum1 += p2 + p3;
            o[t][0] *= al0; o[t][1] *= al0; o[t][2] *= al1; o[t][3] *= al1;
            const int col = t * 8 + ql * 2;
            float2 w0; w0.x = tf32r(p0); w0.y = tf32r(p1);
            *(float2*)&Ps[rloc * 68 + col] = w0;
            float2 w1; w1.x = tf32r(p2); w1.y = tf32r(p3);
            *(float2*)&Ps[(rloc + 8) * 68 + col] = w1;
        }
        sum0 += __shfl_xor_sync(0xffffffffu, sum0, 1);
        sum0 += __shfl_xor_sync(0xffffffffu, sum0, 2);
        sum1 += __shfl_xor_sync(0xffffffffu, sum1, 1);
        sum1 += __shfl_xor_sync(0xffffffffu, sum1, 2);
        l0 = l0 * al0 + sum0;
        l1 = l1 * al1 + sum1;
        m0 = mn0; m1 = mn1;
        __syncwarp();   // P rows are warp-private: warp-level sync suffices

        // ---- O += P V : k over 64 tokens, n over 64 head dims ----
#pragma unroll
        for (int ks = 0; ks < 8; ++ks) {
            uint32_t pa[4];
            const int pc = ks * 8 + ql;
            pa[0] = __float_as_uint(Ps[rloc * 68 + pc]);
            pa[1] = __float_as_uint(Ps[(rloc + 8) * 68 + pc]);
            pa[2] = __float_as_uint(Ps[rloc * 68 + pc + 4]);
            pa[3] = __float_as_uint(Ps[(rloc + 8) * 68 + pc + 4]);
#pragma unroll
            for (int t = 0; t < 8; ++t) {
                const uint32_t b0 = __float_as_uint(Vs[(ks * 8 + ql) * 68 + t * 8 + quad]);
                const uint32_t b1 = __float_as_uint(Vs[(ks * 8 + ql + 4) * 68 + t * 8 + quad]);
                mma_tf32(o[t], pa, b0, b1);
            }
        }
        __syncwarp();
    }

    // ---- epilogue: normalize and store ----
    const float inv0 = 1.f / l0;
    const float inv1 = 1.f / l1;
#pragma unroll
    for (int t = 0; t < 8; ++t) {
        const int col = h * HD + t * 8 + ql * 2;
        float2 w;
        w.x = o[t][0] * inv0; w.y = o[t][1] * inv0;
        *(float2*)(y + (rowBase + qrow0) * CC + col) = w;
        w.x = o[t][2] * inv1; w.y = o[t][3] * inv1;
        *(float2*)(y + (rowBase + qrow1) * CC + col) = w;
    }
}

// ----------------------------------------------------------------------------
extern "C" void kernel_launch(void* const* d_in, const int* in_sizes, int n_in,
                              void* d_out, int out_size)
{
    const float *x = nullptr, *w_attn = nullptr, *b_attn = nullptr,
                *w_proj = nullptr, *b_proj = nullptr;
    for (int i = 0; i < n_in; ++i) {
        const int s = in_sizes[i];
        const float* p = (const float*)d_in[i];
        if      (s == MM * CC)   x      = p;
        else if (s == CC * NQKV) w_attn = p;
        else if (s == NQKV)      b_attn = p;
        else if (s == CC * CC)   w_proj = p;
        else if (s == CC)        b_proj = p;
    }
    float* out = (float*)d_out;

    float *qkv = nullptr, *y = nullptr;
    cudaGetSymbolAddress((void**)&qkv, g_qkv);
    cudaGetSymbolAddress((void**)&y, g_y);

    cudaFuncSetAttribute(flash_attn_tf32_kernel,
                         cudaFuncAttributeMaxDynamicSharedMemorySize,
                         (int)FA_SMEM_BYTES);

    dim3 blk(256);
    // 1) QKV projection (fp32 sgemm)
    sgemm_bias_kernel<<<dim3(NQKV / 128, MM / 128), blk>>>(
        x, w_attn, b_attn, qkv, MM, NQKV, CC);
    // 2) causal flash attention (tf32 tensor cores)
    flash_attn_tf32_kernel<<<dim3(TT / 128, HH, BB), blk, FA_SMEM_BYTES>>>(qkv, y);
    // 3) output projection (fp32 sgemm)
    sgemm_bias_kernel<<<dim3(CC / 128, MM / 128), blk>>>(
        y, w_proj, b_proj, out, MM, CC, CC);
}

// round 4
// speedup vs baseline: 3.0063x; 1.5912x over previous
#include <cuda_runtime.h>
#include <math.h>
#include <stdint.h>

// Problem constants
#define BB   2
#define TT   4096
#define CC   768
#define HH   12
#define HD   64
#define MM   (BB*TT)        // 8192 rows
#define NQKV (3*CC)         // 2304

// Scratch (no cudaMalloc allowed)
__device__ float g_qkv[(size_t)MM * NQKV];
__device__ float g_y[(size_t)MM * CC];

// ----------------------------------------------------------------------------
// TF32 helpers
// ----------------------------------------------------------------------------
__device__ __forceinline__ float tf32r(float x) {
    uint32_t r;
    asm("cvt.rna.tf32.f32 %0, %1;" : "=r"(r) : "f"(x));
    return __uint_as_float(r);
}

__device__ __forceinline__ void mma_tf32(float* d, const uint32_t* a,
                                         uint32_t b0, uint32_t b1) {
    asm volatile(
        "mma.sync.aligned.m16n8k8.row.col.f32.tf32.tf32.f32 "
        "{%0,%1,%2,%3}, {%4,%5,%6,%7}, {%8,%9}, {%0,%1,%2,%3};\n"
        : "+f"(d[0]), "+f"(d[1]), "+f"(d[2]), "+f"(d[3])
        : "r"(a[0]), "r"(a[1]), "r"(a[2]), "r"(a[3]), "r"(b0), "r"(b1));
}

// ----------------------------------------------------------------------------
// TF32 tensor-core GEMM: C[M,N] = A[M,K] @ B[K,N] + bias[N]
// Block 128x128, BK=16, 8 warps (2m x 4n), each warp 64x32.
// Smem stride 140: conflict-free fragment reads (bank = (12*ql+quad)%32 all
// distinct), <=2-way on stores. Register prefetch pipeline over K.
// Requires M%128==0, N%128==0, K%16==0.
// ----------------------------------------------------------------------------
__global__ __launch_bounds__(256)
void gemm_tf32_bias(const float* __restrict__ A, const float* __restrict__ Bm,
                    const float* __restrict__ bias, float* __restrict__ Cm,
                    int M, int N, int K)
{
    __shared__ float As[16][140];   // k-major A tile
    __shared__ float Bs[16][140];   // k-major B tile

    const int tid  = threadIdx.x;
    const int lane = tid & 31, warp = tid >> 5;
    const int quad = lane >> 2, ql = lane & 3;
    const int wm = (warp & 1) * 64;          // warp m-offset in block
    const int wn = (warp >> 1) * 32;         // warp n-offset in block
    const int cm = blockIdx.y * 128, cn = blockIdx.x * 128;

    // gmem load mapping (coalesced)
    const int arow = tid >> 2, acol = (tid & 3) << 2;   // A: rows arow, arow+64
    const int brow = tid >> 5, bcol = (tid & 31) << 2;  // B: rows brow, brow+8

    const float* Ab = A + (size_t)cm * K;
    const float* Bb = Bm + cn;

    float acc[4][4][4];
#pragma unroll
    for (int mt = 0; mt < 4; ++mt)
#pragma unroll
        for (int nt = 0; nt < 4; ++nt)
#pragma unroll
            for (int f = 0; f < 4; ++f) acc[mt][nt][f] = 0.f;

    // prefetch tile 0
    float4 pa0 = *(const float4*)(Ab + (size_t)arow * K + acol);
    float4 pa1 = *(const float4*)(Ab + (size_t)(arow + 64) * K + acol);
    float4 pb0 = *(const float4*)(Bb + (size_t)brow * N + bcol);
    float4 pb1 = *(const float4*)(Bb + (size_t)(brow + 8) * N + bcol);

    const int NK = K >> 4;
    for (int kt = 0; kt < NK; ++kt) {
        // commit prefetched tile to smem (tf32-converted, A transposed to k-major)
        As[acol + 0][arow]      = tf32r(pa0.x);
        As[acol + 1][arow]      = tf32r(pa0.y);
        As[acol + 2][arow]      = tf32r(pa0.z);
        As[acol + 3][arow]      = tf32r(pa0.w);
        As[acol + 0][arow + 64] = tf32r(pa1.x);
        As[acol + 1][arow + 64] = tf32r(pa1.y);
        As[acol + 2][arow + 64] = tf32r(pa1.z);
        As[acol + 3][arow + 64] = tf32r(pa1.w);
        float4 tb;
        tb.x = tf32r(pb0.x); tb.y = tf32r(pb0.y);
        tb.z = tf32r(pb0.z); tb.w = tf32r(pb0.w);
        *(float4*)&Bs[brow][bcol] = tb;
        tb.x = tf32r(pb1.x); tb.y = tf32r(pb1.y);
        tb.z = tf32r(pb1.z); tb.w = tf32r(pb1.w);
        *(float4*)&Bs[brow + 8][bcol] = tb;
        __syncthreads();

        // issue next tile's loads (overlap with MMA below)
        if (kt + 1 < NK) {
            const int k0 = (kt + 1) << 4;
            pa0 = *(const float4*)(Ab + (size_t)arow * K + k0 + acol);
            pa1 = *(const float4*)(Ab + (size_t)(arow + 64) * K + k0 + acol);
            pb0 = *(const float4*)(Bb + (size_t)(k0 + brow) * N + bcol);
            pb1 = *(const float4*)(Bb + (size_t)(k0 + brow + 8) * N + bcol);
        }

        // compute 128x128x16
#pragma unroll
        for (int ks = 0; ks < 2; ++ks) {
            const int kk = ks * 8;
            uint32_t af[4][4];
#pragma unroll
            for (int mt = 0; mt < 4; ++mt) {
                const int mb = wm + mt * 16;
                af[mt][0] = __float_as_uint(As[kk + ql][mb + quad]);
                af[mt][1] = __float_as_uint(As[kk + ql][mb + quad + 8]);
                af[mt][2] = __float_as_uint(As[kk + ql + 4][mb + quad]);
                af[mt][3] = __float_as_uint(As[kk + ql + 4][mb + quad + 8]);
            }
#pragma unroll
            for (int nt = 0; nt < 4; ++nt) {
                const uint32_t b0 = __float_as_uint(Bs[kk + ql][wn + nt * 8 + quad]);
                const uint32_t b1 = __float_as_uint(Bs[kk + ql + 4][wn + nt * 8 + quad]);
#pragma unroll
                for (int mt = 0; mt < 4; ++mt)
                    mma_tf32(acc[mt][nt], af[mt], b0, b1);
            }
        }
        __syncthreads();
    }

    // epilogue: bias + store
#pragma unroll
    for (int mt = 0; mt < 4; ++mt) {
        const int r0 = cm + wm + mt * 16 + quad;
#pragma unroll
        for (int nt = 0; nt < 4; ++nt) {
            const int c = cn + wn + nt * 8 + ql * 2;
            const float bx = bias[c], by = bias[c + 1];
            float2 w;
            w.x = acc[mt][nt][0] + bx; w.y = acc[mt][nt][1] + by;
            *(float2*)(Cm + (size_t)r0 * N + c) = w;
            w.x = acc[mt][nt][2] + bx; w.y = acc[mt][nt][3] + by;
            *(float2*)(Cm + (size_t)(r0 + 8) * N + c) = w;
        }
    }
}

// ----------------------------------------------------------------------------
// Flash attention, tf32 tensor-core version (unchanged from R1 winner).
// ----------------------------------------------------------------------------
#define FA_SMEM_BYTES ((128 + 64 + 64) * 68 * sizeof(float))

__global__ __launch_bounds__(256)
void flash_attn_tf32_kernel(const float* __restrict__ qkv, float* __restrict__ y)
{
    extern __shared__ float sm[];
    float* Qs = sm;                    // [128][68], reused as Ps
    float* Ks = sm + 128 * 68;         // [64][68]
    float* Vs = Ks + 64 * 68;          // [64][68]

    const int tid  = threadIdx.x;
    const int warp = tid >> 5;
    const int lane = tid & 31;
    const int quad = lane >> 2;
    const int ql   = lane & 3;
    const int qb = blockIdx.x;
    const int h  = blockIdx.y;
    const int b  = blockIdx.z;
    const int q0 = qb * 128;
    const size_t rowBase = (size_t)b * TT;
    const int qOff = h * HD, kOff = CC + h * HD, vOff = 2 * CC + h * HD;

#pragma unroll
    for (int p = 0; p < 8; ++p) {
        const int f4 = tid + 256 * p;
        const int r = f4 >> 4, c = (f4 & 15) << 2;
        const float4 v = *(const float4*)(qkv + (rowBase + q0 + r) * NQKV + qOff + c);
        Qs[r * 68 + c + 0] = tf32r(v.x);
        Qs[r * 68 + c + 1] = tf32r(v.y);
        Qs[r * 68 + c + 2] = tf32r(v.z);
        Qs[r * 68 + c + 3] = tf32r(v.w);
    }
    __syncthreads();

    const int rloc = warp * 16 + quad;
    uint32_t qa[8][4];
#pragma unroll
    for (int ks = 0; ks < 8; ++ks) {
        const int c = ks * 8 + ql;
        qa[ks][0] = __float_as_uint(Qs[rloc * 68 + c]);
        qa[ks][1] = __float_as_uint(Qs[(rloc + 8) * 68 + c]);
        qa[ks][2] = __float_as_uint(Qs[rloc * 68 + c + 4]);
        qa[ks][3] = __float_as_uint(Qs[(rloc + 8) * 68 + c + 4]);
    }

    float m0 = -INFINITY, m1 = -INFINITY, l0 = 0.f, l1 = 0.f;
    float o[8][4];
#pragma unroll
    for (int t = 0; t < 8; ++t) { o[t][0] = o[t][1] = o[t][2] = o[t][3] = 0.f; }

    const int qrow0 = q0 + warp * 16 + quad;
    const int qrow1 = qrow0 + 8;
    const float C2 = 0.18033688011112042f;   // log2(e) / sqrt(64)

    const int nkt = (q0 >> 6) + 2;
    for (int kt = 0; kt < nkt; ++kt) {
        const int k0 = kt << 6;
        __syncthreads();
#pragma unroll
        for (int p = 0; p < 4; ++p) {
            const int f4 = tid + 256 * p;
            const int r = f4 >> 4, c = (f4 & 15) << 2;
            const size_t g = (rowBase + k0 + r) * NQKV;
            const float4 kv = *(const float4*)(qkv + g + kOff + c);
            Ks[r * 68 + c + 0] = tf32r(kv.x);
            Ks[r * 68 + c + 1] = tf32r(kv.y);
            Ks[r * 68 + c + 2] = tf32r(kv.z);
            Ks[r * 68 + c + 3] = tf32r(kv.w);
            const float4 vv = *(const float4*)(qkv + g + vOff + c);
            Vs[r * 68 + c + 0] = tf32r(vv.x);
            Vs[r * 68 + c + 1] = tf32r(vv.y);
            Vs[r * 68 + c + 2] = tf32r(vv.z);
            Vs[r * 68 + c + 3] = tf32r(vv.w);
        }
        __syncthreads();

        float sacc[8][4];
#pragma unroll
        for (int t = 0; t < 8; ++t) { sacc[t][0] = sacc[t][1] = sacc[t][2] = sacc[t][3] = 0.f; }
#pragma unroll
        for (int ks = 0; ks < 8; ++ks) {
#pragma unroll
            for (int t = 0; t < 8; ++t) {
                const uint32_t b0 = __float_as_uint(Ks[(t * 8 + quad) * 68 + ks * 8 + ql]);
                const uint32_t b1 = __float_as_uint(Ks[(t * 8 + quad) * 68 + ks * 8 + ql + 4]);
                mma_tf32(sacc[t], qa[ks], b0, b1);
            }
        }

        float rm0 = -INFINITY, rm1 = -INFINITY;
#pragma unroll
        for (int t = 0; t < 8; ++t) {
            const int gc = k0 + t * 8 + ql * 2;
            float v0 = sacc[t][0] * C2; if (gc     > qrow0) v0 = -INFINITY;
            float v1 = sacc[t][1] * C2; if (gc + 1 > qrow0) v1 = -INFINITY;
            float v2 = sacc[t][2] * C2; if (gc     > qrow1) v2 = -INFINITY;
            float v3 = sacc[t][3] * C2; if (gc + 1 > qrow1) v3 = -INFINITY;
            sacc[t][0] = v0; sacc[t][1] = v1; sacc[t][2] = v2; sacc[t][3] = v3;
            rm0 = fmaxf(rm0, fmaxf(v0, v1));
            rm1 = fmaxf(rm1, fmaxf(v2, v3));
        }
        rm0 = fmaxf(rm0, __shfl_xor_sync(0xffffffffu, rm0, 1));
        rm0 = fmaxf(rm0, __shfl_xor_sync(0xffffffffu, rm0, 2));
        rm1 = fmaxf(rm1, __shfl_xor_sync(0xffffffffu, rm1, 1));
        rm1 = fmaxf(rm1, __shfl_xor_sync(0xffffffffu, rm1, 2));
        const float mn0 = fmaxf(m0, rm0);
        const float mn1 = fmaxf(m1, rm1);
        const float al0 = exp2f(m0 - mn0);
        const float al1 = exp2f(m1 - mn1);

        float* Ps = Qs;
        float sum0 = 0.f, sum1 = 0.f;
#pragma unroll
        for (int t = 0; t < 8; ++t) {
            const float p0 = exp2f(sacc[t][0] - mn0);
            const float p1 = exp2f(sacc[t][1] - mn0);
            const float p2 = exp2f(sacc[t][2] - mn1);
            const float p3 = exp2f(sacc[t][3] - mn1);
            sum0 += p0 + p1; sum1 += p2 + p3;
            o[t][0] *= al0; o[t][1] *= al0; o[t][2] *= al1; o[t][3] *= al1;
            const int col = t * 8 + ql * 2;
            float2 w0; w0.x = tf32r(p0); w0.y = tf32r(p1);
            *(float2*)&Ps[rloc * 68 + col] = w0;
            float2 w1; w1.x = tf32r(p2); w1.y = tf32r(p3);
            *(float2*)&Ps[(rloc + 8) * 68 + col] = w1;
        }
        sum0 += __shfl_xor_sync(0xffffffffu, sum0, 1);
        sum0 += __shfl_xor_sync(0xffffffffu, sum0, 2);
        sum1 += __shfl_xor_sync(0xffffffffu, sum1, 1);
        sum1 += __shfl_xor_sync(0xffffffffu, sum1, 2);
        l0 = l0 * al0 + sum0;
        l1 = l1 * al1 + sum1;
        m0 = mn0; m1 = mn1;
        __syncwarp();

#pragma unroll
        for (int ks = 0; ks < 8; ++ks) {
            uint32_t pa[4];
            const int pc = ks * 8 + ql;
            pa[0] = __float_as_uint(Ps[rloc * 68 + pc]);
            pa[1] = __float_as_uint(Ps[(rloc + 8) * 68 + pc]);
            pa[2] = __float_as_uint(Ps[rloc * 68 + pc + 4]);
            pa[3] = __float_as_uint(Ps[(rloc + 8) * 68 + pc + 4]);
#pragma unroll
            for (int t = 0; t < 8; ++t) {
                const uint32_t b0 = __float_as_uint(Vs[(ks * 8 + ql) * 68 + t * 8 + quad]);
                const uint32_t b1 = __float_as_uint(Vs[(ks * 8 + ql + 4) * 68 + t * 8 + quad]);
                mma_tf32(o[t], pa, b0, b1);
            }
        }
        __syncwarp();
    }

    const float inv0 = 1.f / l0;
    const float inv1 = 1.f / l1;
#pragma unroll
    for (int t = 0; t < 8; ++t) {
        const int col = h * HD + t * 8 + ql * 2;
        float2 w;
        w.x = o[t][0] * inv0; w.y = o[t][1] * inv0;
        *(float2*)(y + (rowBase + qrow0) * CC + col) = w;
        w.x = o[t][2] * inv1; w.y = o[t][3] * inv1;
        *(float2*)(y + (rowBase + qrow1) * CC + col) = w;
    }
}

// ----------------------------------------------------------------------------
extern "C" void kernel_launch(void* const* d_in, const int* in_sizes, int n_in,
                              void* d_out, int out_size)
{
    const float *x = nullptr, *w_attn = nullptr, *b_attn = nullptr,
                *w_proj = nullptr, *b_proj = nullptr;
    for (int i = 0; i < n_in; ++i) {
        const int s = in_sizes[i];
        const float* p = (const float*)d_in[i];
        if      (s == MM * CC)   x      = p;
        else if (s == CC * NQKV) w_attn = p;
        else if (s == NQKV)      b_attn = p;
        else if (s == CC * CC)   w_proj = p;
        else if (s == CC)        b_proj = p;
    }
    float* out = (float*)d_out;

    float *qkv = nullptr, *y = nullptr;
    cudaGetSymbolAddress((void**)&qkv, g_qkv);
    cudaGetSymbolAddress((void**)&y, g_y);

    cudaFuncSetAttribute(flash_attn_tf32_kernel,
                         cudaFuncAttributeMaxDynamicSharedMemorySize,
                         (int)FA_SMEM_BYTES);

    dim3 blk(256);
    // 1) QKV projection (tf32 tensor cores)
    gemm_tf32_bias<<<dim3(NQKV / 128, MM / 128), blk>>>(
        x, w_attn, b_attn, qkv, MM, NQKV, CC);
    // 2) causal flash attention (tf32 tensor cores)
    flash_attn_tf32_kernel<<<dim3(TT / 128, HH, BB), blk, FA_SMEM_BYTES>>>(qkv, y);
    // 3) output projection (tf32 tensor cores)
    gemm_tf32_bias<<<dim3(CC / 128, MM / 128), blk>>>(
        y, w_proj, b_proj, out, MM, CC, CC);
}